// round 11
// baseline (speedup 1.0000x reference)
#include <cuda_runtime.h>
#include <cuda_bf16.h>
#include <cstdint>

#define NCLASS 1024
#define DIM    256
#define KSZ    8
#define NSAMP  8192
#define TTILE  16         // 16x16 tiles of 64
#define TS     64         // tile size
#define NPAIR  136        // upper-triangle tile count

// ---------------- scratch (no allocations allowed) ----------------
__device__ __align__(16) __nv_bfloat16 g_cbf[NCLASS * DIM];
__device__ float g_sq[NCLASS];
__device__ float g_pc[NCLASS];       // per-class dist_pc partials
__device__ float g_ph[NPAIR];        // per-tile hinge partials

__device__ __forceinline__ uint32_t smem_u32(const void* p) {
    uint32_t a;
    asm("{ .reg .u64 t; cvta.to.shared.u64 t, %1; cvt.u32.u64 %0, t; }" : "=r"(a) : "l"(p));
    return a;
}
__device__ __forceinline__ void ldm_x4(uint32_t* r, uint32_t addr) {
    asm volatile("ldmatrix.sync.aligned.m8n8.x4.shared.b16 {%0,%1,%2,%3}, [%4];"
                 : "=r"(r[0]), "=r"(r[1]), "=r"(r[2]), "=r"(r[3]) : "r"(addr));
}
__device__ __forceinline__ void mma16816(float* d, const uint32_t* a, uint32_t b0, uint32_t b1) {
    asm volatile(
        "mma.sync.aligned.m16n8k16.row.col.f32.bf16.bf16.f32 "
        "{%0,%1,%2,%3}, {%4,%5,%6,%7}, {%8,%9}, {%0,%1,%2,%3};"
        : "+f"(d[0]), "+f"(d[1]), "+f"(d[2]), "+f"(d[3])
        : "r"(a[0]), "r"(a[1]), "r"(a[2]), "r"(a[3]), "r"(b0), "r"(b1));
}
__device__ __forceinline__ float warp_sum(float v) {
#pragma unroll
    for (int o = 16; o; o >>= 1) v += __shfl_xor_sync(0xffffffffu, v, o);
    return v;
}

// ---------------- kernel 1: warp-per-class (256 CTAs x 4 warps) ----------------
// Lane owns 8 contiguous dims. Uses unit-vector algebra:
//   dist_pc(r) = sqrt(2 - 2 * (xn_r . cen) / |cen|),  |cen|^2 = (sum_r xn_r . cen) / 8
__global__ void __launch_bounds__(128) class_kernel(const float* __restrict__ x) {
    int t = threadIdx.x;
    int wid = t >> 5, lane = t & 31;
    int c = blockIdx.x * 4 + wid;

    const float4* base = (const float4*)(x + (size_t)c * KSZ * DIM) + lane * 2;

    // batch ALL 16 LDG.128 up front (MLP 16)
    float v[KSZ][8];
#pragma unroll
    for (int r = 0; r < KSZ; r++) {
        float4 a = base[r * (DIM / 4)];
        float4 b = base[r * (DIM / 4) + 1];
        v[r][0] = a.x; v[r][1] = a.y; v[r][2] = a.z; v[r][3] = a.w;
        v[r][4] = b.x; v[r][5] = b.y; v[r][6] = b.z; v[r][7] = b.w;
    }

    // row sum-squares, interleaved cascade
    float ss[KSZ];
#pragma unroll
    for (int r = 0; r < KSZ; r++) {
        float s = 0.0f;
#pragma unroll
        for (int i = 0; i < 8; i++) s = fmaf(v[r][i], v[r][i], s);
        ss[r] = s;
    }
#pragma unroll
    for (int o = 16; o; o >>= 1) {
#pragma unroll
        for (int r = 0; r < KSZ; r++) ss[r] += __shfl_xor_sync(0xffffffffu, ss[r], o);
    }
    float inv[KSZ];
#pragma unroll
    for (int r = 0; r < KSZ; r++) inv[r] = rsqrtf(ss[r]);

    // center = sum_r v[r]*inv[r] / 8  (raw rows kept; xn never materialized)
    float cen[8];
#pragma unroll
    for (int i = 0; i < 8; i++) {
        float s = 0.0f;
#pragma unroll
        for (int r = 0; r < KSZ; r++) s = fmaf(v[r][i], inv[r], s);
        cen[i] = s * (1.0f / KSZ);
    }

    // bf16 center store (16B per lane, coalesced)
    {
        uint32_t pk[4];
#pragma unroll
        for (int i = 0; i < 4; i++) {
            __nv_bfloat162 p = __float22bfloat162_rn(make_float2(cen[2 * i], cen[2 * i + 1]));
            pk[i] = *(uint32_t*)&p;
        }
        *(uint4*)(g_cbf + (size_t)c * DIM + lane * 8) = make_uint4(pk[0], pk[1], pk[2], pk[3]);
    }

    // rawdot_r = v_r . cen ; one interleaved cascade
    float rd[KSZ];
#pragma unroll
    for (int r = 0; r < KSZ; r++) {
        float s = 0.0f;
#pragma unroll
        for (int i = 0; i < 8; i++) s = fmaf(v[r][i], cen[i], s);
        rd[r] = s;
    }
#pragma unroll
    for (int o = 16; o; o >>= 1) {
#pragma unroll
        for (int r = 0; r < KSZ; r++) rd[r] += __shfl_xor_sync(0xffffffffu, rd[r], o);
    }

    // dotc_r = xn_r . cen = inv_r * rawdot_r ;  |cen|^2 = sum_r dotc_r / 8
    float dotc[KSZ];
    float c2 = 0.0f;
#pragma unroll
    for (int r = 0; r < KSZ; r++) {
        dotc[r] = inv[r] * rd[r];
        c2 += dotc[r];
    }
    c2 *= (1.0f / KSZ);
    float cinv = rsqrtf(c2);

    float pcsum = 0.0f;
#pragma unroll
    for (int r = 0; r < KSZ; r++)
        pcsum += sqrtf(fmaxf(2.0f - 2.0f * dotc[r] * cinv, 0.0f));

    if (lane == 0) {
        g_sq[c] = c2;
        g_pc[c] = pcsum;
    }
}

// ---------------- kernel 2: bf16 MMA 64x64 pair tiles (no atomics) ----------------
// smem tiles: 64 rows x 256 bf16 (512B rows), 16B segs XOR-swizzled:
// byte = row*512 + ((seg ^ (row&7)) << 4)
#define SMA_BYTES 32768
#define SM_TOTAL  (2 * SMA_BYTES)

__global__ void __launch_bounds__(256, 1) pair_kernel() {
    int t = threadIdx.x;
    int wid = t >> 5, lane = t & 31;

    // closed-form triangular bid -> (bi, bj): off(bi) = bi*(33-bi)/2
    int bid = blockIdx.x;
    int bi = (int)((33.0f - sqrtf(fmaf(-8.0f, (float)bid, 1089.0f))) * 0.5f);
    if (bi * (33 - bi) / 2 > bid) bi--;                       // float fixups
    if ((bi + 1) * (32 - bi) / 2 + bi + 1 <= bid + 1 && bi < 15 &&
        (bi + 1) * (33 - (bi + 1)) / 2 <= bid) bi++;
    int bj = bi + (bid - bi * (33 - bi) / 2);

    extern __shared__ __align__(16) char smem[];
    uint32_t sA = smem_u32(smem);
    uint32_t sB = sA + SMA_BYTES;

    __shared__ float s_sqi[TS], s_sqj[TS];
    __shared__ float rs[8];

    {
        const uint4* gA = (const uint4*)(g_cbf + (size_t)bi * TS * DIM);
        const uint4* gB = (const uint4*)(g_cbf + (size_t)bj * TS * DIM);
#pragma unroll
        for (int it = 0; it < 8; it++) {
            int idx = t + 256 * it;          // 0..2047 segs per tile
            int row = idx >> 5;
            int seg = idx & 31;
            uint32_t o = (uint32_t)(row * 512 + ((seg ^ (row & 7)) << 4));
            *(uint4*)(smem + o) = gA[idx];
            *(uint4*)(smem + SMA_BYTES + o) = gB[idx];
        }
    }
    if (t < TS) s_sqi[t] = g_sq[bi * TS + t];
    else if (t < 2 * TS) s_sqj[t - TS] = g_sq[bj * TS + (t - TS)];
    __syncthreads();

    // MMA mainloop: warp tile 32x16 (2 warps M x 4 warps N)
    int wm = wid >> 2, wn = wid & 3;
    int m0 = wm * 32, n0 = wn * 16;
    int lr = lane & 15, lh = lane >> 4;

    float acc[2][2][4];
#pragma unroll
    for (int a = 0; a < 2; a++)
#pragma unroll
        for (int b = 0; b < 2; b++)
#pragma unroll
            for (int e = 0; e < 4; e++) acc[a][b][e] = 0.0f;

#pragma unroll
    for (int kk = 0; kk < 16; kk++) {
        uint32_t af[2][4], bf[4];
        int seg = kk * 2 + lh;
#pragma unroll
        for (int ma = 0; ma < 2; ma++) {
            int row = m0 + ma * 16 + lr;
            ldm_x4(af[ma], sA + row * 512 + ((seg ^ (row & 7)) << 4));
        }
        {
            int row = n0 + lr;
            ldm_x4(bf, sB + row * 512 + ((seg ^ (row & 7)) << 4));
        }
#pragma unroll
        for (int ma = 0; ma < 2; ma++) {
            mma16816(acc[ma][0], af[ma], bf[0], bf[2]);
            mma16816(acc[ma][1], af[ma], bf[1], bf[3]);
        }
    }

    // epilogue: hinge over fragments
    int g = lane >> 2, tg = lane & 3;
    bool diag = (bi == bj);
    float local = 0.0f;
#pragma unroll
    for (int ma = 0; ma < 2; ma++) {
#pragma unroll
        for (int nn = 0; nn < 2; nn++) {
            int r0 = m0 + ma * 16 + g;
            int c0 = n0 + nn * 8 + tg * 2;
#pragma unroll
            for (int e = 0; e < 4; e++) {
                int r = r0 + (e >> 1) * 8;
                int c = c0 + (e & 1);
                float dot = acc[ma][nn][e];
                float d2 = s_sqi[r] + s_sqj[c] - 2.0f * dot;
                float d = sqrtf(fmaxf(d2, 1e-12f));
                float h = fmaxf(0.7f - d, 0.0f);
                if (!diag || c > r) local += h;
            }
        }
    }
    local = warp_sum(local);
    if (lane == 0) rs[wid] = local;
    __syncthreads();
    if (t == 0) {
        float s = 0.0f;
#pragma unroll
        for (int w2 = 0; w2 < 8; w2++) s += rs[w2];
        g_ph[bid] = s;   // plain store — no atomics
    }
}

// ---------------- kernel 3: finalize ----------------
__global__ void __launch_bounds__(256) final_kernel(float* __restrict__ out) {
    int t = threadIdx.x;
    int wid = t >> 5, lane = t & 31;
    float s1 = 0.0f, s2 = 0.0f;
#pragma unroll
    for (int i = t; i < NCLASS; i += 256) s1 += g_pc[i];
    if (t < NPAIR) s2 += g_ph[t];
    s1 = warp_sum(s1);
    s2 = warp_sum(s2);
    __shared__ float r1[8], r2[8];
    if (lane == 0) { r1[wid] = s1; r2[wid] = s2; }
    __syncthreads();
    if (t == 0) {
        float a = 0.0f, b = 0.0f;
#pragma unroll
        for (int w = 0; w < 8; w++) { a += r1[w]; b += r2[w]; }
        float pc = a * (1.0f / (float)NSAMP);
        float an = b * (2.0f * (float)KSZ / ((float)(NSAMP - KSZ) * (float)NCLASS));
        out[0] = pc + an;
        out[1] = pc;
        out[2] = an;
    }
}

extern "C" void kernel_launch(void* const* d_in, const int* in_sizes, int n_in,
                              void* d_out, int out_size) {
    const float* x = (const float*)d_in[0];
    float* out = (float*)d_out;

    static bool attr_set = false;
    if (!attr_set) {
        cudaFuncSetAttribute(pair_kernel, cudaFuncAttributeMaxDynamicSharedMemorySize, SM_TOTAL);
        attr_set = true;
    }

    class_kernel<<<NCLASS / 4, 128>>>(x);
    pair_kernel<<<NPAIR, 256, SM_TOTAL>>>();
    final_kernel<<<1, 256>>>(out);
}

// round 14
// speedup vs baseline: 1.2941x; 1.2941x over previous
#include <cuda_runtime.h>
#include <cuda_bf16.h>
#include <cstdint>

#define NCLASS 1024
#define DIM    256
#define KSZ    8
#define NSAMP  8192
#define TTILE  16         // 16x16 tiles of 64
#define TS     64         // tile size
#define NPAIR  136        // upper-triangle tile count

// ---------------- scratch (no allocations allowed) ----------------
__device__ __align__(16) __nv_bfloat16 g_cbf[NCLASS * DIM];
__device__ float g_sq[NCLASS];
__device__ float g_pc[NCLASS];       // per-class dist_pc partials
__device__ float g_ph[NPAIR];        // per-tile hinge partials

__device__ __forceinline__ uint32_t smem_u32(const void* p) {
    uint32_t a;
    asm("{ .reg .u64 t; cvta.to.shared.u64 t, %1; cvt.u32.u64 %0, t; }" : "=r"(a) : "l"(p));
    return a;
}
__device__ __forceinline__ void ldm_x4(uint32_t* r, uint32_t addr) {
    asm volatile("ldmatrix.sync.aligned.m8n8.x4.shared.b16 {%0,%1,%2,%3}, [%4];"
                 : "=r"(r[0]), "=r"(r[1]), "=r"(r[2]), "=r"(r[3]) : "r"(addr));
}
__device__ __forceinline__ void mma16816(float* d, const uint32_t* a, uint32_t b0, uint32_t b1) {
    asm volatile(
        "mma.sync.aligned.m16n8k16.row.col.f32.bf16.bf16.f32 "
        "{%0,%1,%2,%3}, {%4,%5,%6,%7}, {%8,%9}, {%0,%1,%2,%3};"
        : "+f"(d[0]), "+f"(d[1]), "+f"(d[2]), "+f"(d[3])
        : "r"(a[0]), "r"(a[1]), "r"(a[2]), "r"(a[3]), "r"(b0), "r"(b1));
}
__device__ __forceinline__ float warp_sum(float v) {
#pragma unroll
    for (int o = 16; o; o >>= 1) v += __shfl_xor_sync(0xffffffffu, v, o);
    return v;
}

// ---------------- kernel 1: quarter-class-per-warp (512 CTAs x 8 warps) ----------------
// CTA handles 2 classes; 4 warps per class, 2 rows per warp. Lane owns dims [8*lane, 8*lane+8).
__global__ void __launch_bounds__(256) class_kernel(const float* __restrict__ x) {
    int t = threadIdx.x;
    int wid = t >> 5, lane = t & 31;
    int cl = wid >> 2;                 // class slot in CTA (0/1)
    int q  = wid & 3;                  // quarter: rows 2q, 2q+1
    int c  = blockIdx.x * 2 + cl;
    int wg = cl * 4;                   // first warp of this class

    __shared__ float s_part[8][256];   // per-warp partial centers: [w][i*32+lane]
    __shared__ float s_dotc[8][2];     // per-warp normalized dots (2 rows each)

    const float4* base = (const float4*)(x + ((size_t)c * KSZ + q * 2) * DIM) + lane * 2;

    // 4 LDG.128, all issued up front
    float v0[8], v1[8];
    {
        float4 a0 = base[0];
        float4 b0 = base[1];
        float4 a1 = base[DIM / 4];
        float4 b1 = base[DIM / 4 + 1];
        v0[0] = a0.x; v0[1] = a0.y; v0[2] = a0.z; v0[3] = a0.w;
        v0[4] = b0.x; v0[5] = b0.y; v0[6] = b0.z; v0[7] = b0.w;
        v1[0] = a1.x; v1[1] = a1.y; v1[2] = a1.z; v1[3] = a1.w;
        v1[4] = b1.x; v1[5] = b1.y; v1[6] = b1.z; v1[7] = b1.w;
    }

    // row sum-squares, interleaved cascade
    float s0 = 0.0f, s1 = 0.0f;
#pragma unroll
    for (int i = 0; i < 8; i++) { s0 = fmaf(v0[i], v0[i], s0); s1 = fmaf(v1[i], v1[i], s1); }
#pragma unroll
    for (int o = 16; o; o >>= 1) {
        s0 += __shfl_xor_sync(0xffffffffu, s0, o);
        s1 += __shfl_xor_sync(0xffffffffu, s1, o);
    }
    float inv0 = rsqrtf(s0), inv1 = rsqrtf(s1);

    // partial center (2 rows), to smem (bank = lane, conflict-free)
#pragma unroll
    for (int i = 0; i < 8; i++)
        s_part[wid][i * 32 + lane] = fmaf(v0[i], inv0, v1[i] * inv1);
    __syncthreads();

    // full center (each warp of the class computes it redundantly)
    float cen[8];
#pragma unroll
    for (int i = 0; i < 8; i++) {
        cen[i] = (s_part[wg][i * 32 + lane] + s_part[wg + 1][i * 32 + lane] +
                  s_part[wg + 2][i * 32 + lane] + s_part[wg + 3][i * 32 + lane]) * (1.0f / KSZ);
    }

    // q==0 warp stores bf16 center (16B/lane, coalesced)
    if (q == 0) {
        uint32_t pk[4];
#pragma unroll
        for (int i = 0; i < 4; i++) {
            __nv_bfloat162 p = __float22bfloat162_rn(make_float2(cen[2 * i], cen[2 * i + 1]));
            pk[i] = *(uint32_t*)&p;
        }
        *(uint4*)(g_cbf + (size_t)c * DIM + lane * 8) = make_uint4(pk[0], pk[1], pk[2], pk[3]);
    }

    // raw dots of this warp's 2 rows with the center
    float r0 = 0.0f, r1 = 0.0f;
#pragma unroll
    for (int i = 0; i < 8; i++) { r0 = fmaf(v0[i], cen[i], r0); r1 = fmaf(v1[i], cen[i], r1); }
#pragma unroll
    for (int o = 16; o; o >>= 1) {
        r0 += __shfl_xor_sync(0xffffffffu, r0, o);
        r1 += __shfl_xor_sync(0xffffffffu, r1, o);
    }
    if (lane == 0) {
        s_dotc[wid][0] = inv0 * r0;    // xn_r . cen
        s_dotc[wid][1] = inv1 * r1;
    }
    __syncthreads();

    // q==0 warp finalizes its class: lanes 0..7 hold the 8 dotc values
    if (q == 0) {
        float dv = (lane < 8) ? s_dotc[wg + (lane >> 1)][lane & 1] : 0.0f;
        float c2 = warp_sum(dv) * (1.0f / KSZ);     // |cen|^2
        float cinv = rsqrtf(c2);
        float pcv = (lane < 8) ? sqrtf(fmaxf(2.0f - 2.0f * dv * cinv, 0.0f)) : 0.0f;
        float pcsum = warp_sum(pcv);
        if (lane == 0) {
            g_sq[c] = c2;
            g_pc[c] = pcsum;
        }
    }
}

// ---------------- kernel 2: bf16 MMA 64x64 pair tiles (no atomics) ----------------
// smem tiles: 64 rows x 256 bf16 (512B rows), 16B segs XOR-swizzled:
// byte = row*512 + ((seg ^ (row&7)) << 4)
#define SMA_BYTES 32768
#define SM_TOTAL  (2 * SMA_BYTES)

__global__ void __launch_bounds__(256, 1) pair_kernel() {
    int t = threadIdx.x;
    int wid = t >> 5, lane = t & 31;

    // triangular bid -> (bi, bj), bj >= bi
    int bid = blockIdx.x;
    int bi = 0, off = 0;
    while (bid >= off + (TTILE - bi)) { off += TTILE - bi; bi++; }
    int bj = bi + (bid - off);

    extern __shared__ __align__(16) char smem[];
    uint32_t sA = smem_u32(smem);
    uint32_t sB = sA + SMA_BYTES;

    __shared__ float s_sqi[TS], s_sqj[TS];
    __shared__ float rs[8];

    {
        const uint4* gA = (const uint4*)(g_cbf + (size_t)bi * TS * DIM);
        const uint4* gB = (const uint4*)(g_cbf + (size_t)bj * TS * DIM);
#pragma unroll
        for (int it = 0; it < 8; it++) {
            int idx = t + 256 * it;          // 0..2047 segs per tile
            int row = idx >> 5;
            int seg = idx & 31;
            uint32_t o = (uint32_t)(row * 512 + ((seg ^ (row & 7)) << 4));
            *(uint4*)(smem + o) = gA[idx];
            *(uint4*)(smem + SMA_BYTES + o) = gB[idx];
        }
    }
    if (t < TS) s_sqi[t] = g_sq[bi * TS + t];
    else if (t < 2 * TS) s_sqj[t - TS] = g_sq[bj * TS + (t - TS)];
    __syncthreads();

    // MMA mainloop: warp tile 32x16 (2 warps M x 4 warps N)
    int wm = wid >> 2, wn = wid & 3;
    int m0 = wm * 32, n0 = wn * 16;
    int lr = lane & 15, lh = lane >> 4;

    float acc[2][2][4];
#pragma unroll
    for (int a = 0; a < 2; a++)
#pragma unroll
        for (int b = 0; b < 2; b++)
#pragma unroll
            for (int e = 0; e < 4; e++) acc[a][b][e] = 0.0f;

#pragma unroll
    for (int kk = 0; kk < 16; kk++) {
        uint32_t af[2][4], bf[4];
        int seg = kk * 2 + lh;
#pragma unroll
        for (int ma = 0; ma < 2; ma++) {
            int row = m0 + ma * 16 + lr;
            ldm_x4(af[ma], sA + row * 512 + ((seg ^ (row & 7)) << 4));
        }
        {
            int row = n0 + lr;
            ldm_x4(bf, sB + row * 512 + ((seg ^ (row & 7)) << 4));
        }
#pragma unroll
        for (int ma = 0; ma < 2; ma++) {
            mma16816(acc[ma][0], af[ma], bf[0], bf[2]);
            mma16816(acc[ma][1], af[ma], bf[1], bf[3]);
        }
    }

    // epilogue: hinge over fragments
    int g = lane >> 2, tg = lane & 3;
    bool diag = (bi == bj);
    float local = 0.0f;
#pragma unroll
    for (int ma = 0; ma < 2; ma++) {
#pragma unroll
        for (int nn = 0; nn < 2; nn++) {
            int r0 = m0 + ma * 16 + g;
            int c0 = n0 + nn * 8 + tg * 2;
#pragma unroll
            for (int e = 0; e < 4; e++) {
                int r = r0 + (e >> 1) * 8;
                int c = c0 + (e & 1);
                float dot = acc[ma][nn][e];
                float d2 = s_sqi[r] + s_sqj[c] - 2.0f * dot;
                float d = sqrtf(fmaxf(d2, 1e-12f));
                float h = fmaxf(0.7f - d, 0.0f);
                if (!diag || c > r) local += h;
            }
        }
    }
    local = warp_sum(local);
    if (lane == 0) rs[wid] = local;
    __syncthreads();
    if (t == 0) {
        float s = 0.0f;
#pragma unroll
        for (int w2 = 0; w2 < 8; w2++) s += rs[w2];
        g_ph[bid] = s;   // plain store — no atomics
    }
}

// ---------------- kernel 3: finalize ----------------
__global__ void __launch_bounds__(256) final_kernel(float* __restrict__ out) {
    int t = threadIdx.x;
    int wid = t >> 5, lane = t & 31;
    float s1 = 0.0f, s2 = 0.0f;
#pragma unroll
    for (int i = t; i < NCLASS; i += 256) s1 += g_pc[i];
    if (t < NPAIR) s2 += g_ph[t];
    s1 = warp_sum(s1);
    s2 = warp_sum(s2);
    __shared__ float r1[8], r2[8];
    if (lane == 0) { r1[wid] = s1; r2[wid] = s2; }
    __syncthreads();
    if (t == 0) {
        float a = 0.0f, b = 0.0f;
#pragma unroll
        for (int w = 0; w < 8; w++) { a += r1[w]; b += r2[w]; }
        float pc = a * (1.0f / (float)NSAMP);
        float an = b * (2.0f * (float)KSZ / ((float)(NSAMP - KSZ) * (float)NCLASS));
        out[0] = pc + an;
        out[1] = pc;
        out[2] = an;
    }
}

extern "C" void kernel_launch(void* const* d_in, const int* in_sizes, int n_in,
                              void* d_out, int out_size) {
    const float* x = (const float*)d_in[0];
    float* out = (float*)d_out;

    static bool attr_set = false;
    if (!attr_set) {
        cudaFuncSetAttribute(pair_kernel, cudaFuncAttributeMaxDynamicSharedMemorySize, SM_TOTAL);
        attr_set = true;
    }

    class_kernel<<<NCLASS / 2, 256>>>(x);
    pair_kernel<<<NPAIR, 256, SM_TOTAL>>>();
    final_kernel<<<1, 256>>>(out);
}

// round 15
// speedup vs baseline: 1.3233x; 1.0226x over previous
#include <cuda_runtime.h>
#include <cuda_bf16.h>
#include <cstdint>

#define NCLASS 1024
#define DIM    256
#define KSZ    8
#define NSAMP  8192
#define TTILE  16         // 16x16 tiles of 64
#define TS     64         // tile size
#define NPAIR  136        // upper-triangle tile count

// ---------------- scratch (no allocations allowed) ----------------
__device__ __align__(16) __nv_bfloat16 g_cbf[NCLASS * DIM];
__device__ float g_sq[NCLASS];
__device__ float g_pc[NCLASS];       // per-class dist_pc partials
__device__ float g_ph[NPAIR];        // per-tile hinge partials

__device__ __forceinline__ uint32_t smem_u32(const void* p) {
    uint32_t a;
    asm("{ .reg .u64 t; cvta.to.shared.u64 t, %1; cvt.u32.u64 %0, t; }" : "=r"(a) : "l"(p));
    return a;
}
__device__ __forceinline__ void ldm_x4(uint32_t* r, uint32_t addr) {
    asm volatile("ldmatrix.sync.aligned.m8n8.x4.shared.b16 {%0,%1,%2,%3}, [%4];"
                 : "=r"(r[0]), "=r"(r[1]), "=r"(r[2]), "=r"(r[3]) : "r"(addr));
}
__device__ __forceinline__ void mma16816(float* d, const uint32_t* a, uint32_t b0, uint32_t b1) {
    asm volatile(
        "mma.sync.aligned.m16n8k16.row.col.f32.bf16.bf16.f32 "
        "{%0,%1,%2,%3}, {%4,%5,%6,%7}, {%8,%9}, {%0,%1,%2,%3};"
        : "+f"(d[0]), "+f"(d[1]), "+f"(d[2]), "+f"(d[3])
        : "r"(a[0]), "r"(a[1]), "r"(a[2]), "r"(a[3]), "r"(b0), "r"(b1));
}
__device__ __forceinline__ float warp_sum(float v) {
#pragma unroll
    for (int o = 16; o; o >>= 1) v += __shfl_xor_sync(0xffffffffu, v, o);
    return v;
}

// ---------------- kernel 1: warp-per-class (128 CTAs x 8 warps) ----------------
// Lane owns 8 contiguous dims. ALL 16 LDG.128 issued up front (MLP=16) — this
// batching is what buys ~2.7 TB/s effective; row-split variants sink to 1.2.
__global__ void __launch_bounds__(256) class_kernel(const float* __restrict__ x) {
    int t = threadIdx.x;
    int wid = t >> 5, lane = t & 31;
    int c = blockIdx.x * 8 + wid;

    const float4* base = (const float4*)(x + (size_t)c * KSZ * DIM) + lane * 2;

    // batch ALL loads first
    float v[KSZ][8];
#pragma unroll
    for (int r = 0; r < KSZ; r++) {
        float4 a = base[r * (DIM / 4)];
        float4 b = base[r * (DIM / 4) + 1];
        v[r][0] = a.x; v[r][1] = a.y; v[r][2] = a.z; v[r][3] = a.w;
        v[r][4] = b.x; v[r][5] = b.y; v[r][6] = b.z; v[r][7] = b.w;
    }
    // independent row sum-squares, interleaved shuffle cascade
    float ss[KSZ];
#pragma unroll
    for (int r = 0; r < KSZ; r++) {
        float s = 0.0f;
#pragma unroll
        for (int i = 0; i < 8; i++) s = fmaf(v[r][i], v[r][i], s);
        ss[r] = s;
    }
#pragma unroll
    for (int o = 16; o; o >>= 1) {
#pragma unroll
        for (int r = 0; r < KSZ; r++) ss[r] += __shfl_xor_sync(0xffffffffu, ss[r], o);
    }
    float cen[8] = {0, 0, 0, 0, 0, 0, 0, 0};
#pragma unroll
    for (int r = 0; r < KSZ; r++) {
        float inv = rsqrtf(ss[r]);
#pragma unroll
        for (int i = 0; i < 8; i++) {
            v[r][i] *= inv;              // xn
            cen[i] += v[r][i];
        }
    }
#pragma unroll
    for (int i = 0; i < 8; i++) cen[i] *= (1.0f / KSZ);

    // bf16 center store (16B/lane, coalesced)
    {
        uint32_t pk[4];
#pragma unroll
        for (int i = 0; i < 4; i++) {
            __nv_bfloat162 p = __float22bfloat162_rn(make_float2(cen[2 * i], cen[2 * i + 1]));
            pk[i] = *(uint32_t*)&p;
        }
        *(uint4*)(g_cbf + (size_t)c * DIM + lane * 8) = make_uint4(pk[0], pk[1], pk[2], pk[3]);
    }

    float c2 = 0.0f;
#pragma unroll
    for (int i = 0; i < 8; i++) c2 = fmaf(cen[i], cen[i], c2);
    c2 = warp_sum(c2);
    if (lane == 0) g_sq[c] = c2;
    float cinv = rsqrtf(c2);

    float ds[KSZ];
#pragma unroll
    for (int r = 0; r < KSZ; r++) {
        float s = 0.0f;
#pragma unroll
        for (int i = 0; i < 8; i++) {
            float diff = v[r][i] - cen[i] * cinv;
            s = fmaf(diff, diff, s);
        }
        ds[r] = s;
    }
#pragma unroll
    for (int o = 16; o; o >>= 1) {
#pragma unroll
        for (int r = 0; r < KSZ; r++) ds[r] += __shfl_xor_sync(0xffffffffu, ds[r], o);
    }
    float pcsum = 0.0f;
#pragma unroll
    for (int r = 0; r < KSZ; r++) pcsum += sqrtf(ds[r]);
    if (lane == 0) g_pc[c] = pcsum;
}

// ---------------- kernel 2: bf16 MMA 64x64 pair tiles (no atomics) ----------------
// smem tiles: 64 rows x 256 bf16 (512B rows), 16B segs XOR-swizzled:
// byte = row*512 + ((seg ^ (row&7)) << 4)
#define SMA_BYTES 32768
#define SM_TOTAL  (2 * SMA_BYTES)

__global__ void __launch_bounds__(256, 1) pair_kernel() {
    int t = threadIdx.x;
    int wid = t >> 5, lane = t & 31;

    // triangular bid -> (bi, bj), bj >= bi
    int bid = blockIdx.x;
    int bi = 0, off = 0;
    while (bid >= off + (TTILE - bi)) { off += TTILE - bi; bi++; }
    int bj = bi + (bid - off);

    extern __shared__ __align__(16) char smem[];
    uint32_t sA = smem_u32(smem);
    uint32_t sB = sA + SMA_BYTES;

    __shared__ float s_sqi[TS], s_sqj[TS];
    __shared__ float rs[8];

    {
        const uint4* gA = (const uint4*)(g_cbf + (size_t)bi * TS * DIM);
        const uint4* gB = (const uint4*)(g_cbf + (size_t)bj * TS * DIM);
#pragma unroll
        for (int it = 0; it < 8; it++) {
            int idx = t + 256 * it;          // 0..2047 segs per tile
            int row = idx >> 5;
            int seg = idx & 31;
            uint32_t o = (uint32_t)(row * 512 + ((seg ^ (row & 7)) << 4));
            *(uint4*)(smem + o) = gA[idx];
            *(uint4*)(smem + SMA_BYTES + o) = gB[idx];
        }
    }
    if (t < TS) s_sqi[t] = g_sq[bi * TS + t];
    else if (t < 2 * TS) s_sqj[t - TS] = g_sq[bj * TS + (t - TS)];
    __syncthreads();

    // MMA mainloop: warp tile 32x16 (2 warps M x 4 warps N)
    int wm = wid >> 2, wn = wid & 3;
    int m0 = wm * 32, n0 = wn * 16;
    int lr = lane & 15, lh = lane >> 4;

    float acc[2][2][4];
#pragma unroll
    for (int a = 0; a < 2; a++)
#pragma unroll
        for (int b = 0; b < 2; b++)
#pragma unroll
            for (int e = 0; e < 4; e++) acc[a][b][e] = 0.0f;

#pragma unroll
    for (int kk = 0; kk < 16; kk++) {
        uint32_t af[2][4], bf[4];
        int seg = kk * 2 + lh;
#pragma unroll
        for (int ma = 0; ma < 2; ma++) {
            int row = m0 + ma * 16 + lr;
            ldm_x4(af[ma], sA + row * 512 + ((seg ^ (row & 7)) << 4));
        }
        {
            int row = n0 + lr;
            ldm_x4(bf, sB + row * 512 + ((seg ^ (row & 7)) << 4));
        }
#pragma unroll
        for (int ma = 0; ma < 2; ma++) {
            mma16816(acc[ma][0], af[ma], bf[0], bf[2]);
            mma16816(acc[ma][1], af[ma], bf[1], bf[3]);
        }
    }

    // epilogue: hinge over fragments
    int g = lane >> 2, tg = lane & 3;
    bool diag = (bi == bj);
    float local = 0.0f;
#pragma unroll
    for (int ma = 0; ma < 2; ma++) {
#pragma unroll
        for (int nn = 0; nn < 2; nn++) {
            int r0 = m0 + ma * 16 + g;
            int c0 = n0 + nn * 8 + tg * 2;
#pragma unroll
            for (int e = 0; e < 4; e++) {
                int r = r0 + (e >> 1) * 8;
                int c = c0 + (e & 1);
                float dot = acc[ma][nn][e];
                float d2 = s_sqi[r] + s_sqj[c] - 2.0f * dot;
                float d = sqrtf(fmaxf(d2, 1e-12f));
                float h = fmaxf(0.7f - d, 0.0f);
                if (!diag || c > r) local += h;
            }
        }
    }
    local = warp_sum(local);
    if (lane == 0) rs[wid] = local;
    __syncthreads();
    if (t == 0) {
        float s = 0.0f;
#pragma unroll
        for (int w2 = 0; w2 < 8; w2++) s += rs[w2];
        g_ph[bid] = s;   // plain store — no atomics
    }
}

// ---------------- kernel 3: finalize ----------------
__global__ void __launch_bounds__(256) final_kernel(float* __restrict__ out) {
    int t = threadIdx.x;
    int wid = t >> 5, lane = t & 31;
    float s1 = 0.0f, s2 = 0.0f;
#pragma unroll
    for (int i = t; i < NCLASS; i += 256) s1 += g_pc[i];
    if (t < NPAIR) s2 += g_ph[t];
    s1 = warp_sum(s1);
    s2 = warp_sum(s2);
    __shared__ float r1[8], r2[8];
    if (lane == 0) { r1[wid] = s1; r2[wid] = s2; }
    __syncthreads();
    if (t == 0) {
        float a = 0.0f, b = 0.0f;
#pragma unroll
        for (int w = 0; w < 8; w++) { a += r1[w]; b += r2[w]; }
        float pc = a * (1.0f / (float)NSAMP);
        float an = b * (2.0f * (float)KSZ / ((float)(NSAMP - KSZ) * (float)NCLASS));
        out[0] = pc + an;
        out[1] = pc;
        out[2] = an;
    }
}

extern "C" void kernel_launch(void* const* d_in, const int* in_sizes, int n_in,
                              void* d_out, int out_size) {
    const float* x = (const float*)d_in[0];
    float* out = (float*)d_out;

    static bool attr_set = false;
    if (!attr_set) {
        cudaFuncSetAttribute(pair_kernel, cudaFuncAttributeMaxDynamicSharedMemorySize, SM_TOTAL);
        attr_set = true;
    }

    class_kernel<<<NCLASS / 8, 256>>>(x);
    pair_kernel<<<NPAIR, 256, SM_TOTAL>>>();
    final_kernel<<<1, 256>>>(out);
}